// round 14
// baseline (speedup 1.0000x reference)
#include <cuda_runtime.h>
#include <cuda_fp16.h>
#include <cstdint>

#define BS   2
#define SEQ  4096
#define HH   32
#define LLC  64
#define CC   (SEQ/LLC)   // 64
#define RSH  40          // words per half2 table row (32 data + 8 pad)
#define GSTR (HH*64)

__device__ __half g_states[(size_t)BS*CC*HH*64*64];  // [b][c][h][p][n] fp16
__device__ __half g_prefix[(size_t)BS*CC*HH*64*64];  // [b][c][h][p][n] fp16
__device__ __half g_ydiag [(size_t)BS*SEQ*HH*64];    // [b][s][h][p]    fp16

typedef unsigned int u32;

__device__ __forceinline__ u32 f22h(float lo, float hi){
    u32 r; asm("cvt.rn.f16x2.f32 %0, %1, %2;" : "=r"(r) : "f"(hi), "f"(lo)); return r;
}
__device__ __forceinline__ float2 h22f(u32 v){
    __half2 h = *reinterpret_cast<__half2*>(&v);
    return __half22float2(h);
}
// D(16x8,f32) += A(16x16,f16 row) * B(16x8,f16 col)
__device__ __forceinline__ void mma16(float* d, const u32* a, u32 b0, u32 b1){
    asm volatile("mma.sync.aligned.m16n8k16.row.col.f32.f16.f16.f32 "
        "{%0,%1,%2,%3}, {%4,%5,%6,%7}, {%8,%9}, {%0,%1,%2,%3};"
        : "+f"(d[0]), "+f"(d[1]), "+f"(d[2]), "+f"(d[3])
        : "r"(a[0]), "r"(a[1]), "r"(a[2]), "r"(a[3]), "r"(b0), "r"(b1));
}
// skew-paired half2 layout: pair q = 4*(w>>3)+(w&3) holds words w, w+4;
// pair column rotated by r>>2.
__device__ __forceinline__ int WH(int r, int w){
    return 2*(((4*(w>>3)) + (w&3) + (r>>2)) & 15) + ((w>>2)&1);
}
__device__ __forceinline__ void stpw(u32* t, int r, int w, u32 v){
    t[r*RSH + WH(r,w)] = v;
}
__device__ __forceinline__ uint2 ldpairH(const u32* t, int r, int kk, int qc){
    return *(const uint2*)&t[r*RSH + 2*((4*kk + qc + (r>>2)) & 15)];
}
__device__ __forceinline__ void ldfragH(const u32* t, int r, int kk, int qc, u32* a){
    uint2 lo = ldpairH(t, r, kk, qc), hi = ldpairH(t, r+8, kk, qc);
    a[0] = lo.x; a[1] = hi.x; a[2] = lo.y; a[3] = hi.y;
}

// ===========================================================================
// K1: per (b,c,h). 128 thr / 4 warps; warp owns FULL 16 rows x 64 cols.
// G kept in registers between mm1 and mm2 (D-frag == A-frag layout).
// ===========================================================================
__global__ __launch_bounds__(128, 5) void ssd_k1(
    const float* __restrict__ X, const float* __restrict__ A,
    const float* __restrict__ Bm, const float* __restrict__ Cm)
{
    extern __shared__ u32 smw[];
    u32* sXt = smw;                 // [p][s-halves]
    u32* sB  = smw + 64*RSH;        // [s][n-halves]
    u32* sC  = smw + 2*64*RSH;      // [l][n-halves]
    u32* sBt = smw + 3*64*RSH;      // [n][l-halves], dec folded
    float* aA   = (float*)(smw + 4*64*RSH);
    float* el   = aA + 64;
    float* einv = el + 64;
    float* decs = einv + 64;

    const int h = blockIdx.x, c = blockIdx.y, b = blockIdx.z;
    const int tid = threadIdx.x, wid = tid >> 5, lane = tid & 31;
    const int qr = lane >> 2, qc = lane & 3;
    const int m0 = wid * 16;                  // warp's 16 rows
    const int base = ((b*SEQ + c*LLC)*HH + h)*64;

    // phase A: load B, C as half2 (paired layout); aA
    #pragma unroll
    for (int i = tid; i < 1024; i += 128) {
        int row = i >> 4, c4 = (i & 15) << 2;
        int g = base + row*GSTR + c4;
        float4 bv = *(const float4*)&Bm[g];
        float4 cv = *(const float4*)&Cm[g];
        stpw(sB, row, c4>>1,     f22h(bv.x, bv.y));
        stpw(sB, row, (c4>>1)+1, f22h(bv.z, bv.w));
        stpw(sC, row, c4>>1,     f22h(cv.x, cv.y));
        stpw(sC, row, (c4>>1)+1, f22h(cv.z, cv.w));
    }
    if (tid < 64) aA[tid] = A[(b*SEQ + c*LLC + tid)*HH + h];

    // phase C: X transposed straight from global into sXt[p][s-halves]
    #pragma unroll
    for (int m = 0; m < 8; m++) {
        int w = wid*8 + m;                        // s-pair
        const float2 x0 = *(const float2*)&X[base + (2*w)*GSTR + 2*lane];
        const float2 x1 = *(const float2*)&X[base + (2*w+1)*GSTR + 2*lane];
        stpw(sXt, 2*lane,   w, f22h(x0.x, x1.x));
        stpw(sXt, 2*lane+1, w, f22h(x0.y, x1.y));
    }
    __syncthreads();

    if (tid < 64) {
        float s = 0.f, mine = 0.f;
        #pragma unroll
        for (int j = 0; j < 64; j++) { s += aA[j]; if (j == tid) mine = s; }
        el[tid]   = __expf(mine);
        einv[tid] = __expf(-mine);
        decs[tid] = __expf(s - mine);
    }
    __syncthreads();

    // phase D: sBt[n][l-halves] = dec[l]*B[l][n]
    #pragma unroll
    for (int m = 0; m < 8; m++) {
        int w = wid*8 + m;                        // l-pair
        float d0 = decs[2*w], d1 = decs[2*w+1];
        u32 v0 = sB[(2*w)*RSH   + WH(2*w,   lane)];
        u32 v1 = sB[(2*w+1)*RSH + WH(2*w+1, lane)];
        float2 fa = h22f(v0), fb = h22f(v1);
        stpw(sBt, 2*lane,   w, f22h(fa.x*d0, fb.x*d1));
        stpw(sBt, 2*lane+1, w, f22h(fa.y*d0, fb.y*d1));
    }
    __syncthreads();
    // all smem tables final; mm1/mm2/mm3 run sync-free from here

    // ---- mm1: G[l,s] = sum_n C[l,n]*B[s,n]; full 16x64 rows per warp ----
    float g[8][4] = {};
    #pragma unroll
    for (int kk = 0; kk < 4; kk++) {
        u32 a0[4];
        ldfragH(sC, m0+qr, kk, qc, a0);
        #pragma unroll
        for (int t = 0; t < 8; t++) {
            uint2 bb = ldpairH(sB, t*8+qr, kk, qc);
            mma16(g[t], a0, bb.x, bb.y);
        }
    }

    // mask + decay IN REGISTERS -> fp16 A-fragments for mm2
    u32 ha[8][2];
    {
        const int l0v = m0 + qr, l1v = l0v + 8;
        const float e0 = el[l0v], e1 = el[l1v];
        #pragma unroll
        for (int t = 0; t < 8; t++) {
            int s0 = t*8 + 2*qc, s1 = s0 + 1;
            float i0 = einv[s0], i1 = einv[s1];
            float v0 = (s0 <= l0v) ? g[t][0]*e0*i0 : 0.f;
            float v1 = (s1 <= l0v) ? g[t][1]*e0*i1 : 0.f;
            float v2 = (s0 <= l1v) ? g[t][2]*e1*i0 : 0.f;
            float v3 = (s1 <= l1v) ? g[t][3]*e1*i1 : 0.f;
            ha[t][0] = f22h(v0, v1);    // rows qr / qr+8 at s0,s1
            ha[t][1] = f22h(v2, v3);
        }
    }

    // ---- mm2: Y[l,p] = sum_s G[l,s]*X[s,p]; A straight from registers ----
    {
        float y[8][4] = {};
        #pragma unroll
        for (int kk = 0; kk < 4; kk++) {
            u32 a2[4] = { ha[2*kk][0], ha[2*kk][1], ha[2*kk+1][0], ha[2*kk+1][1] };
            #pragma unroll
            for (int t = 0; t < 8; t++) {
                uint2 bb = ldpairH(sXt, t*8+qr, kk, qc);
                mma16(y[t], a2, bb.x, bb.y);
            }
        }
        int row0 = m0 + qr, row1 = m0 + qr + 8;
        #pragma unroll
        for (int t = 0; t < 8; t++) {
            int c0 = t*8 + 2*qc;
            *(u32*)&g_ydiag[base + row0*GSTR + c0] = f22h(y[t][0], y[t][1]);
            *(u32*)&g_ydiag[base + row1*GSTR + c0] = f22h(y[t][2], y[t][3]);
        }
    }

    // ---- mm3: S[p,n] = sum_l Xt[p,l]*(dec[l]*B[l,n]) ----
    {
        float st[8][4] = {};
        #pragma unroll
        for (int kk = 0; kk < 4; kk++) {
            u32 a0[4];
            ldfragH(sXt, m0+qr, kk, qc, a0);
            #pragma unroll
            for (int t = 0; t < 8; t++) {
                uint2 bb = ldpairH(sBt, t*8+qr, kk, qc);
                mma16(st[t], a0, bb.x, bb.y);
            }
        }
        const int sbase = ((b*CC + c)*HH + h)*4096;
        int row0 = m0 + qr, row1 = m0 + qr + 8;
        #pragma unroll
        for (int t = 0; t < 8; t++) {
            int c0 = t*8 + 2*qc;
            *(u32*)&g_states[sbase + row0*64 + c0] = f22h(st[t][0], st[t][1]);
            *(u32*)&g_states[sbase + row1*64 + c0] = f22h(st[t][2], st[t][3]);
        }
    }
}

// ===========================================================================
// K2: inter-chunk scan over fp16 words; fp32 accumulation in registers.
// 256 blocks (4 segments per (b,h)) x 512 threads; prefetched.
// ===========================================================================
__global__ __launch_bounds__(512) void ssd_k2(const float* __restrict__ A)
{
    __shared__ float ea[CC];
    const int blk = blockIdx.x;
    const int seg = blk & 3, bh = blk >> 2, h = bh & 31, b = bh >> 5;
    const int tid = threadIdx.x;

    if (tid < CC) {
        float s = 0.f;
        int ab = (b*SEQ + tid*LLC)*HH + h;
        for (int l = 0; l < LLC; l++) s += A[ab + l*HH];
        ea[tid] = __expf(s);
    }
    __syncthreads();

    const u32* sp = (const u32*)g_states;
    u32* pp = (u32*)g_prefix;
    const int w = seg*512 + tid;                    // word in [0,2048)
    size_t off = ((size_t)(b*CC)*HH + h)*2048 + w;
    float r0 = 0.f, r1 = 0.f;
    u32 v = sp[off];
    for (int z = 0; z < CC; z++) {
        u32 nv = (z+1 < CC) ? sp[off + (size_t)HH*2048] : 0u;
        pp[off] = f22h(r0, r1);
        float2 f = h22f(v);
        float e = ea[z];
        r0 = r0*e + f.x; r1 = r1*e + f.y;
        v = nv;
        off += (size_t)HH*2048;
    }
}

// ===========================================================================
// K3: Y[l,p] = ydiag[l,p] + el[l] * sum_n C[l,n]*St[p,n]  (single fp32 write)
// ===========================================================================
__global__ __launch_bounds__(128) void ssd_k3(
    const float* __restrict__ A, const float* __restrict__ Cm,
    float* __restrict__ Y)
{
    extern __shared__ u32 smw[];
    u32* sC = smw;                 // [l][n-halves]
    u32* sS = smw + 64*RSH;        // [p][n-halves]
    float* aA = (float*)(smw + 2*64*RSH);
    float* el = aA + 64;

    const int h = blockIdx.x, c = blockIdx.y, b = blockIdx.z;
    const int tid = threadIdx.x, wid = tid >> 5, lane = tid & 31;
    const int qr = lane >> 2, qc = lane & 3;
    const int rh = wid >> 1, ch = wid & 1;
    const int rA0 = rh*32, rA1 = rh*32 + 16;
    const int cB = ch*32;
    const int base = ((b*SEQ + c*LLC)*HH + h)*64;
    const int sbase = ((b*CC + c)*HH + h)*4096;

    // C: fp32->fp16 convert; prefix: already half2 words, direct restage
    #pragma unroll
    for (int i = tid; i < 1024; i += 128) {
        int row = i >> 4, c4 = (i & 15) << 2;
        float4 cv = *(const float4*)&Cm[base + row*GSTR + c4];
        stpw(sC, row, c4>>1,     f22h(cv.x, cv.y));
        stpw(sC, row, (c4>>1)+1, f22h(cv.z, cv.w));
        uint2 sv = *(const uint2*)&g_prefix[sbase + row*64 + c4];
        stpw(sS, row, c4>>1,     sv.x);
        stpw(sS, row, (c4>>1)+1, sv.y);
    }
    if (tid < 64) aA[tid] = A[(b*SEQ + c*LLC + tid)*HH + h];
    __syncthreads();
    if (tid < 64) {
        float s = 0.f, mine = 0.f;
        #pragma unroll
        for (int j = 0; j < 64; j++) { s += aA[j]; if (j == tid) mine = s; }
        el[tid] = __expf(mine);
    }
    __syncthreads();

    float y[2][4][4] = {};
    #pragma unroll
    for (int kk = 0; kk < 4; kk++) {
        u32 a0[4], a1[4];
        ldfragH(sC, rA0+qr, kk, qc, a0);
        ldfragH(sC, rA1+qr, kk, qc, a1);
        #pragma unroll
        for (int t = 0; t < 4; t++) {
            uint2 bb = ldpairH(sS, cB + t*8 + qr, kk, qc);
            mma16(y[0][t], a0, bb.x, bb.y);
            mma16(y[1][t], a1, bb.x, bb.y);
        }
    }

    // Y = ydiag + el * acc   (read fp16 stash, single fp32 write)
    #pragma unroll
    for (int mg = 0; mg < 2; mg++) {
        int r0 = rh*32 + mg*16;
        int row0 = r0 + qr, row1 = r0 + qr + 8;
        float e0 = el[row0], e1 = el[row1];
        #pragma unroll
        for (int t = 0; t < 4; t++) {
            int c0 = cB + t*8 + 2*qc;
            float2 d0 = h22f(*(const u32*)&g_ydiag[base + row0*GSTR + c0]);
            float2 d1 = h22f(*(const u32*)&g_ydiag[base + row1*GSTR + c0]);
            *(float2*)&Y[base + row0*GSTR + c0] =
                make_float2(d0.x + e0*y[mg][t][0], d0.y + e0*y[mg][t][1]);
            *(float2*)&Y[base + row1*GSTR + c0] =
                make_float2(d1.x + e1*y[mg][t][2], d1.y + e1*y[mg][t][3]);
        }
    }
}

// ---------------------------------------------------------------------------
extern "C" void kernel_launch(void* const* d_in, const int* in_sizes, int n_in,
                              void* d_out, int out_size)
{
    const float* X  = (const float*)d_in[0];
    const float* A  = (const float*)d_in[1];
    const float* Bm = (const float*)d_in[2];
    const float* Cm = (const float*)d_in[3];
    float* Y = (float*)d_out;

    const int sm1 = (4*64*RSH + 4*64) * 4;   // 41984 B
    const int sm3 = (2*64*RSH + 2*64) * 4;   // 20992 B
    cudaFuncSetAttribute(ssd_k1, cudaFuncAttributeMaxDynamicSharedMemorySize, sm1);
    cudaFuncSetAttribute(ssd_k3, cudaFuncAttributeMaxDynamicSharedMemorySize, sm3);

    dim3 grid(HH, CC, BS);
    ssd_k1<<<grid, 128, sm1>>>(X, A, Bm, Cm);
    ssd_k2<<<BS*HH*4, 512>>>(A);
    ssd_k3<<<grid, 128, sm3>>>(A, Cm, Y);
}